// round 9
// baseline (speedup 1.0000x reference)
#include <cuda_runtime.h>
#include <cstdint>

// GptOssTopKRouter via mma.sync bf16 (compute_103-safe tensor path).
// logits = hs[16384,2880] @ w[128,2880]^T + bias -> top-4 -> softmax.
// Output f32: scores[T*4] ++ indices[T*4].
//
// fp32 via 3-plane bf16 Dekker split, 6 plane-products; main product (a0b0)
// in its own fp32 accumulator set, corrections in a second set.
// R9: cp.async raw-fp32 staging (frees 16 prefetch regs, no LDG stalls in
// mainloop), B-fragment double buffer, cvt split across k-steps.

#define TT    16384
#define HH    2880
#define EE    128
#define TOPK  4
#define BM    128
#define KC    32
#define NCH   (HH / KC)        // 90

#define PITCH  80              // bytes/row (conflict-free for ldmatrix)
#define PLB    (128 * PITCH)   // 10240 B per plane
#define STG    (6 * PLB)       // A0 A1 A2 B0 B1 B2 = 61440 B
#define SMOFF  512
#define LPITCH 132

#define RAWSLOT 48                       // 32B data + 16B pad per thread
#define RAWMAT  (512 * RAWSLOT)          // 24576 B (one matrix, one stage)
#define RAWSTG  (2 * RAWMAT)             // A + B
#define RAWOFF  (SMOFF + 2 * STG)        // 123392
#define SMEM_BYTES (RAWOFF + 2 * RAWSTG) // 221696

__device__ __forceinline__ uint32_t s2u(const void* p) {
    uint32_t a;
    asm("{ .reg .u64 t; cvta.to.shared.u64 t, %1; cvt.u32.u64 %0, t; }"
        : "=r"(a) : "l"(p));
    return a;
}
__device__ __forceinline__ uint32_t pack_bf16x2(float hi, float lo) {
    uint32_t r;
    asm("cvt.rn.bf16x2.f32 %0, %1, %2;" : "=r"(r) : "f"(hi), "f"(lo));
    return r;
}
__device__ __forceinline__ void ldmx4(uint32_t* r, uint32_t addr) {
    asm volatile("ldmatrix.sync.aligned.m8n8.x4.shared.b16 {%0,%1,%2,%3}, [%4];"
                 : "=r"(r[0]), "=r"(r[1]), "=r"(r[2]), "=r"(r[3]) : "r"(addr));
}
__device__ __forceinline__ void mma16(float* c, const uint32_t* a, const uint32_t* b) {
    asm("mma.sync.aligned.m16n8k16.row.col.f32.bf16.bf16.f32 "
        "{%0,%1,%2,%3}, {%4,%5,%6,%7}, {%8,%9}, {%0,%1,%2,%3};"
        : "+f"(c[0]), "+f"(c[1]), "+f"(c[2]), "+f"(c[3])
        : "r"(a[0]), "r"(a[1]), "r"(a[2]), "r"(a[3]), "r"(b[0]), "r"(b[1]));
}
__device__ __forceinline__ void cpa16(uint32_t dst, const float* src) {
    asm volatile("cp.async.cg.shared.global [%0], [%1], 16;"
                 :: "r"(dst), "l"(src) : "memory");
}
#define CP_COMMIT() asm volatile("cp.async.commit_group;" ::: "memory")
#define CP_WAIT1()  asm volatile("cp.async.wait_group 1;" ::: "memory")
#define CP_WAIT0()  asm volatile("cp.async.wait_group 0;" ::: "memory")

// 8 fp32 -> 3 bf16 planes (Dekker exact split), one 16B store per plane.
__device__ __forceinline__ void cvt8(const float4& f0, const float4& f1,
                                     char* p0, char* p1, char* p2) {
    float x[8] = {f0.x, f0.y, f0.z, f0.w, f1.x, f1.y, f1.z, f1.w};
    uint32_t q0[4], q1[4], q2[4];
    #pragma unroll
    for (int q = 0; q < 4; q++) {
        float a = x[2 * q], b = x[2 * q + 1];
        uint32_t h = pack_bf16x2(b, a);             // lo=bf16(a), hi=bf16(b)
        float ha = __uint_as_float(h << 16);
        float hb = __uint_as_float(h & 0xFFFF0000u);
        float ra = a - ha, rb = b - hb;             // exact
        uint32_t m = pack_bf16x2(rb, ra);
        float ma = __uint_as_float(m << 16);
        float mb = __uint_as_float(m & 0xFFFF0000u);
        q2[q] = pack_bf16x2(rb - mb, ra - ma);      // exact residual
        q0[q] = h; q1[q] = m;
    }
    *reinterpret_cast<uint4*>(p0) = make_uint4(q0[0], q0[1], q0[2], q0[3]);
    *reinterpret_cast<uint4*>(p1) = make_uint4(q1[0], q1[1], q1[2], q1[3]);
    *reinterpret_cast<uint4*>(p2) = make_uint4(q2[0], q2[1], q2[2], q2[3]);
}

__global__ __launch_bounds__(512, 1)
void router_hmma(const float* __restrict__ hs,
                 const float* __restrict__ wt,
                 const float* __restrict__ bias,
                 float* __restrict__ out,
                 int write_idx)
{
    extern __shared__ char smem[];
    float* sbias = reinterpret_cast<float*>(smem);
    float* slog  = reinterpret_cast<float*>(smem + SMOFF);
    const uint32_t sb = s2u(smem);

    const int tid  = threadIdx.x;
    const int wid  = tid >> 5;
    const int lane = tid & 31;
    const int m0   = blockIdx.x * BM;

    if (tid < EE) sbias[tid] = bias[tid];

    // ---- convert mapping: 4 threads per row, 8 fp32 each ----
    const int crow = tid >> 2;
    const int ckq  = (tid & 3) * 8;
    const float* tA = hs + (size_t)(m0 + crow) * HH + ckq;
    const float* tB = wt + (size_t)crow * HH + ckq;
    const int cvtoff = crow * PITCH + ckq * 2;
    const uint32_t rawbase = sb + RAWOFF + (uint32_t)tid * RAWSLOT;

    // ---- mma mapping: 16 warps = 4M x 4N; warp tile 32x32 ----
    const int moff = (wid & 3) * 32;
    const int noff = (wid >> 2) * 32;
    const int mt8  = lane >> 3;
    const int mr   = lane & 7;
    uint32_t aoff[2], boff[2];
    #pragma unroll
    for (int mt = 0; mt < 2; mt++)
        aoff[mt] = (uint32_t)((moff + mt * 16 + ((mt8 & 1) << 3) + mr) * PITCH
                              + (((mt8 >> 1) << 3) << 1));
    #pragma unroll
    for (int q = 0; q < 2; q++)
        boff[q] = (uint32_t)((noff + q * 16 + ((mt8 >> 1) << 3) + mr) * PITCH
                             + (((mt8 & 1) << 3) << 1));

    float cM[2][4][4], cC[2][4][4];
    #pragma unroll
    for (int i = 0; i < 2; i++)
        #pragma unroll
        for (int j = 0; j < 4; j++)
            #pragma unroll
            for (int q = 0; q < 4; q++) { cM[i][j][q] = 0.0f; cC[i][j][q] = 0.0f; }

    // ---- async issue / convert helpers (lambdas keep mappings in scope) ----
    auto issue = [&](int c) {
        uint32_t dA = rawbase + (uint32_t)((c & 1) ? RAWSTG : 0);
        const float* sA = tA + (size_t)c * KC;
        cpa16(dA, sA); cpa16(dA + 16, sA + 4);
        uint32_t dB = dA + RAWMAT;
        const float* sB = tB + (size_t)c * KC;
        cpa16(dB, sB); cpa16(dB + 16, sB + 4);
        CP_COMMIT();
    };
    auto cvtA = [&](int c) {
        const char* r = smem + RAWOFF + ((c & 1) ? RAWSTG : 0) + tid * RAWSLOT;
        float4 f0 = *reinterpret_cast<const float4*>(r);
        float4 f1 = *reinterpret_cast<const float4*>(r + 16);
        char* st = smem + SMOFF + (c & 1) * STG;
        cvt8(f0, f1, st + cvtoff, st + PLB + cvtoff, st + 2 * PLB + cvtoff);
    };
    auto cvtB = [&](int c) {
        const char* r = smem + RAWOFF + ((c & 1) ? RAWSTG : 0) + RAWMAT
                        + tid * RAWSLOT;
        float4 f0 = *reinterpret_cast<const float4*>(r);
        float4 f1 = *reinterpret_cast<const float4*>(r + 16);
        char* st = smem + SMOFF + (c & 1) * STG + 3 * PLB;
        cvt8(f0, f1, st + cvtoff, st + PLB + cvtoff, st + 2 * PLB + cvtoff);
    };

    // ---- prologue: async chunks 0,1; convert chunk 0 ----
    issue(0);
    issue(1);
    CP_WAIT1();            // chunk 0 landed
    cvtA(0);
    cvtB(0);
    __syncthreads();

    for (int c = 0; c < NCH; c++) {
        const int s = c & 1;
        const uint32_t Ab = sb + SMOFF + s * STG;
        const uint32_t Bb = Ab + 3 * PLB;

        #pragma unroll
        for (int ks = 0; ks < 2; ks++) {
            const uint32_t kb = ks * 32;       // 16 K-cols = 32 bytes

            uint32_t A0[2][4], A1[2][4], A2[2][4], Bf0[8], Bf1[8];
            #pragma unroll
            for (int q = 0; q < 2; q++) ldmx4(&Bf0[q * 4], Bb + boff[q] + kb);
            #pragma unroll
            for (int mt = 0; mt < 2; mt++) ldmx4(A0[mt], Ab + aoff[mt] + kb);
            #pragma unroll
            for (int mt = 0; mt < 2; mt++) ldmx4(A1[mt], Ab + PLB + aoff[mt] + kb);
            #pragma unroll
            for (int mt = 0; mt < 2; mt++) ldmx4(A2[mt], Ab + 2 * PLB + aoff[mt] + kb);

            // B plane 1 prefetched into the second buffer
            #pragma unroll
            for (int q = 0; q < 2; q++) ldmx4(&Bf1[q * 4], Bb + PLB + boff[q] + kb);

            // plane 0: A0->cM, A1->cC, A2->cC
            #pragma unroll
            for (int mt = 0; mt < 2; mt++)
                #pragma unroll
                for (int nt = 0; nt < 4; nt++) {
                    mma16(cM[mt][nt], A0[mt], &Bf0[nt * 2]);
                    mma16(cC[mt][nt], A1[mt], &Bf0[nt * 2]);
                    mma16(cC[mt][nt], A2[mt], &Bf0[nt * 2]);
                }

            // overlapped: async issue + convert (A at ks0, B at ks1)
            if (ks == 0) {
                if (c + 2 < NCH) issue(c + 2);
                if (c + 1 < NCH) {
                    if (c + 2 < NCH) { CP_WAIT1(); } else { CP_WAIT0(); }
                    cvtA(c + 1);
                }
            } else {
                if (c + 1 < NCH) cvtB(c + 1);
            }

            // plane 2 into Bf0 (its plane-0 reads have drained by now)
            #pragma unroll
            for (int q = 0; q < 2; q++)
                ldmx4(&Bf0[q * 4], Bb + 2 * PLB + boff[q] + kb);

            // plane 1: A0->cC, A1->cC
            #pragma unroll
            for (int mt = 0; mt < 2; mt++)
                #pragma unroll
                for (int nt = 0; nt < 4; nt++) {
                    mma16(cC[mt][nt], A0[mt], &Bf1[nt * 2]);
                    mma16(cC[mt][nt], A1[mt], &Bf1[nt * 2]);
                }

            // plane 2: A0->cC
            #pragma unroll
            for (int mt = 0; mt < 2; mt++)
                #pragma unroll
                for (int nt = 0; nt < 4; nt++)
                    mma16(cC[mt][nt], A0[mt], &Bf0[nt * 2]);
        }

        __syncthreads();   // stage s reads done; stage s^1 writes visible
    }

    // ---- combine accumulators, write logits [128][132] (stage area reused) ----
    #pragma unroll
    for (int mt = 0; mt < 2; mt++)
        #pragma unroll
        for (int nt = 0; nt < 4; nt++) {
            int r0  = moff + mt * 16 + (lane >> 2);
            int col = noff + nt * 8 + 2 * (lane & 3);
            slog[r0 * LPITCH + col]           = cM[mt][nt][0] + cC[mt][nt][0];
            slog[r0 * LPITCH + col + 1]       = cM[mt][nt][1] + cC[mt][nt][1];
            slog[(r0 + 8) * LPITCH + col]     = cM[mt][nt][2] + cC[mt][nt][2];
            slog[(r0 + 8) * LPITCH + col + 1] = cM[mt][nt][3] + cC[mt][nt][3];
        }

    __syncthreads();

    // ---- top-4 + softmax: one thread per token ----
    if (tid < BM) {
        const float* row = slog + tid * LPITCH;
        float v0 = -1e30f, v1 = -1e30f, v2 = -1e30f, v3 = -1e30f;
        int   i0 = 0,      i1 = 0,      i2 = 0,      i3 = 0;
        #pragma unroll 4
        for (int e = 0; e < EE; e++) {
            float v = row[e] + sbias[e];
            if (v > v3) {               // strict > keeps earliest index on ties
                if (v > v2) {
                    v3 = v2; i3 = i2;
                    if (v > v1) {
                        v2 = v1; i2 = i1;
                        if (v > v0) { v1 = v0; i1 = i0; v0 = v; i0 = e; }
                        else        { v1 = v;  i1 = e; }
                    } else { v2 = v; i2 = e; }
                } else { v3 = v; i3 = e; }
            }
        }
        float e1 = expf(v1 - v0);
        float e2 = expf(v2 - v0);
        float e3 = expf(v3 - v0);
        float inv = 1.0f / (1.0f + e1 + e2 + e3);

        const int t = m0 + tid;
        float* so = out + (size_t)t * TOPK;
        so[0] = inv; so[1] = e1 * inv; so[2] = e2 * inv; so[3] = e3 * inv;
        if (write_idx) {
            float* io = out + (size_t)TT * TOPK + (size_t)t * TOPK;
            io[0] = (float)i0; io[1] = (float)i1;
            io[2] = (float)i2; io[3] = (float)i3;
        }
    }
}

extern "C" void kernel_launch(void* const* d_in, const int* in_sizes, int n_in,
                              void* d_out, int out_size) {
    const float* hs   = (const float*)d_in[0];
    const float* wt   = (const float*)d_in[1];
    const float* bias = (const float*)d_in[2];
    float* out = (float*)d_out;

    const int write_idx = (out_size >= 2 * TT * TOPK) ? 1 : 0;

    cudaFuncSetAttribute(router_hmma,
                         cudaFuncAttributeMaxDynamicSharedMemorySize, SMEM_BYTES);
    router_hmma<<<TT / BM, 512, SMEM_BYTES>>>(hs, wt, bias, out, write_idx);
}

// round 11
// speedup vs baseline: 1.0862x; 1.0862x over previous
#include <cuda_runtime.h>
#include <cstdint>

// GptOssTopKRouter via mma.sync bf16 (compute_103-safe tensor path).
// logits = hs[16384,2880] @ w[128,2880]^T + bias -> top-4 -> softmax.
// Output f32: scores[T*4] ++ indices[T*4].
//
// fp32 via 3-plane bf16 Dekker split, 6 plane-products; main product (a0b0)
// in its own fp32 accumulator set, corrections in a second set.
// R11 (= R10 resubmit after infra failure): BM=64 / 256 threads / 2 CTAs per
// SM -> one CTA's MMAs cover the other CTA's barrier+convert stalls.
// Register LDG prefetch with A/B liveness split across k-steps.

#define TT    16384
#define HH    2880
#define EE    128
#define TOPK  4
#define BM    64
#define KC    32
#define NCH   (HH / KC)        // 90

#define PITCH  80              // bytes/row (conflict-free for ldmatrix/STS)
#define APLB   (64  * PITCH)   // 5120  B per A plane
#define BPLB   (128 * PITCH)   // 10240 B per B plane
#define STG    (3 * APLB + 3 * BPLB)   // 46080 B: A0 A1 A2 B0 B1 B2
#define BOFS   (3 * APLB)
#define SMOFF  512
#define LPITCH 132
#define SMEM_BYTES (SMOFF + 2 * STG)   // 92672 (logits reuse stage area)

__device__ __forceinline__ uint32_t s2u(const void* p) {
    uint32_t a;
    asm("{ .reg .u64 t; cvta.to.shared.u64 t, %1; cvt.u32.u64 %0, t; }"
        : "=r"(a) : "l"(p));
    return a;
}
__device__ __forceinline__ uint32_t pack_bf16x2(float hi, float lo) {
    uint32_t r;
    asm("cvt.rn.bf16x2.f32 %0, %1, %2;" : "=r"(r) : "f"(hi), "f"(lo));
    return r;
}
__device__ __forceinline__ void ldmx4(uint32_t* r, uint32_t addr) {
    asm volatile("ldmatrix.sync.aligned.m8n8.x4.shared.b16 {%0,%1,%2,%3}, [%4];"
                 : "=r"(r[0]), "=r"(r[1]), "=r"(r[2]), "=r"(r[3]) : "r"(addr));
}
__device__ __forceinline__ void mma16(float* c, const uint32_t* a, const uint32_t* b) {
    asm("mma.sync.aligned.m16n8k16.row.col.f32.bf16.bf16.f32 "
        "{%0,%1,%2,%3}, {%4,%5,%6,%7}, {%8,%9}, {%0,%1,%2,%3};"
        : "+f"(c[0]), "+f"(c[1]), "+f"(c[2]), "+f"(c[3])
        : "r"(a[0]), "r"(a[1]), "r"(a[2]), "r"(a[3]), "r"(b[0]), "r"(b[1]));
}

// 8 fp32 -> 3 bf16 planes (Dekker exact split), one 16B store per plane.
__device__ __forceinline__ void cvt8(const float4& f0, const float4& f1,
                                     char* p0, char* p1, char* p2) {
    float x[8] = {f0.x, f0.y, f0.z, f0.w, f1.x, f1.y, f1.z, f1.w};
    uint32_t q0[4], q1[4], q2[4];
    #pragma unroll
    for (int q = 0; q < 4; q++) {
        float a = x[2 * q], b = x[2 * q + 1];
        uint32_t h = pack_bf16x2(b, a);             // lo=bf16(a), hi=bf16(b)
        float ha = __uint_as_float(h << 16);
        float hb = __uint_as_float(h & 0xFFFF0000u);
        float ra = a - ha, rb = b - hb;             // exact
        uint32_t m = pack_bf16x2(rb, ra);
        float ma = __uint_as_float(m << 16);
        float mb = __uint_as_float(m & 0xFFFF0000u);
        q2[q] = pack_bf16x2(rb - mb, ra - ma);      // exact residual
        q0[q] = h; q1[q] = m;
    }
    *reinterpret_cast<uint4*>(p0) = make_uint4(q0[0], q0[1], q0[2], q0[3]);
    *reinterpret_cast<uint4*>(p1) = make_uint4(q1[0], q1[1], q1[2], q1[3]);
    *reinterpret_cast<uint4*>(p2) = make_uint4(q2[0], q2[1], q2[2], q2[3]);
}

__global__ __launch_bounds__(256, 2)
void router_hmma(const float* __restrict__ hs,
                 const float* __restrict__ wt,
                 const float* __restrict__ bias,
                 float* __restrict__ out,
                 int write_idx)
{
    extern __shared__ char smem[];
    float* sbias = reinterpret_cast<float*>(smem);
    float* slog  = reinterpret_cast<float*>(smem + SMOFF);
    const uint32_t sb = s2u(smem);

    const int tid  = threadIdx.x;
    const int wid  = tid >> 5;
    const int lane = tid & 31;
    const int m0   = blockIdx.x * BM;

    if (tid < EE) sbias[tid] = bias[tid];

    // ---- convert mapping ----
    // A: 256 slots (64 rows x 4), 8 fp32 each.
    const int arow = tid >> 2;
    const int akq  = (tid & 3) * 8;
    const float* gA = hs + (size_t)(m0 + arow) * HH + akq;
    const int aoffc = arow * PITCH + akq * 2;
    // B: 512 slots (128 rows x 4); thread handles slots tid and tid+256.
    const float* gB0 = wt + (size_t)(tid >> 2) * HH + akq;
    const float* gB1 = gB0 + (size_t)64 * HH;
    const int boffc0 = (tid >> 2) * PITCH + akq * 2;
    const int boffc1 = boffc0 + 64 * PITCH;

    // ---- mma mapping: 8 warps = 2M x 4N; warp tile 32x32 ----
    const int moff = (wid & 1) * 32;
    const int noff = (wid >> 1) * 32;
    const int mt8  = lane >> 3;
    const int mr   = lane & 7;
    uint32_t aoff[2], boff[2];
    #pragma unroll
    for (int mt = 0; mt < 2; mt++)
        aoff[mt] = (uint32_t)((moff + mt * 16 + ((mt8 & 1) << 3) + mr) * PITCH
                              + (((mt8 >> 1) << 3) << 1));
    #pragma unroll
    for (int q = 0; q < 2; q++)
        boff[q] = (uint32_t)((noff + q * 16 + ((mt8 >> 1) << 3) + mr) * PITCH
                             + (((mt8 & 1) << 3) << 1));

    float cM[2][4][4], cC[2][4][4];
    #pragma unroll
    for (int i = 0; i < 2; i++)
        #pragma unroll
        for (int j = 0; j < 4; j++)
            #pragma unroll
            for (int q = 0; q < 4; q++) { cM[i][j][q] = 0.0f; cC[i][j][q] = 0.0f; }

    // ---- prefetch registers: A 8 fp32, B 16 fp32 ----
    float4 pa0, pa1, pb0, pb1, pb2, pb3;

    // prologue: chunk 0 -> stage0, hold chunk 1 in regs
    pa0 = *reinterpret_cast<const float4*>(gA);
    pa1 = *reinterpret_cast<const float4*>(gA + 4);
    pb0 = *reinterpret_cast<const float4*>(gB0);
    pb1 = *reinterpret_cast<const float4*>(gB0 + 4);
    pb2 = *reinterpret_cast<const float4*>(gB1);
    pb3 = *reinterpret_cast<const float4*>(gB1 + 4);
    {
        char* st = smem + SMOFF;
        cvt8(pa0, pa1, st + aoffc, st + APLB + aoffc, st + 2 * APLB + aoffc);
        char* bt = st + BOFS;
        cvt8(pb0, pb1, bt + boffc0, bt + BPLB + boffc0, bt + 2 * BPLB + boffc0);
        cvt8(pb2, pb3, bt + boffc1, bt + BPLB + boffc1, bt + 2 * BPLB + boffc1);
    }
    pa0 = *reinterpret_cast<const float4*>(gA + KC);
    pa1 = *reinterpret_cast<const float4*>(gA + KC + 4);
    pb0 = *reinterpret_cast<const float4*>(gB0 + KC);
    pb1 = *reinterpret_cast<const float4*>(gB0 + KC + 4);
    pb2 = *reinterpret_cast<const float4*>(gB1 + KC);
    pb3 = *reinterpret_cast<const float4*>(gB1 + KC + 4);
    __syncthreads();

    for (int c = 0; c < NCH; c++) {
        const int s = c & 1;
        const uint32_t Ab = sb + SMOFF + s * STG;
        const uint32_t Bb = Ab + BOFS;

        #pragma unroll
        for (int ks = 0; ks < 2; ks++) {
            const uint32_t kb = ks * 32;       // 16 K-cols = 32 bytes

            uint32_t A0[2][4], A1[2][4], A2[2][4], Bf[8];
            #pragma unroll
            for (int q = 0; q < 2; q++) ldmx4(&Bf[q * 4], Bb + boff[q] + kb);
            #pragma unroll
            for (int mt = 0; mt < 2; mt++) ldmx4(A0[mt], Ab + aoff[mt] + kb);
            #pragma unroll
            for (int mt = 0; mt < 2; mt++) ldmx4(A1[mt], Ab + APLB + aoff[mt] + kb);
            #pragma unroll
            for (int mt = 0; mt < 2; mt++) ldmx4(A2[mt], Ab + 2 * APLB + aoff[mt] + kb);

            // plane 0: A0->cM, A1->cC, A2->cC
            #pragma unroll
            for (int mt = 0; mt < 2; mt++)
                #pragma unroll
                for (int nt = 0; nt < 4; nt++) {
                    mma16(cM[mt][nt], A0[mt], &Bf[nt * 2]);
                    mma16(cC[mt][nt], A1[mt], &Bf[nt * 2]);
                    mma16(cC[mt][nt], A2[mt], &Bf[nt * 2]);
                }

            // overlapped convert/prefetch (A at ks0, B at ks1)
            if (ks == 0) {
                if (c + 1 < NCH) {
                    char* st = smem + SMOFF + (s ^ 1) * STG;
                    cvt8(pa0, pa1, st + aoffc, st + APLB + aoffc,
                         st + 2 * APLB + aoffc);
                }
            } else {
                if (c + 1 < NCH) {
                    char* bt = smem + SMOFF + (s ^ 1) * STG + BOFS;
                    cvt8(pb0, pb1, bt + boffc0, bt + BPLB + boffc0,
                         bt + 2 * BPLB + boffc0);
                    cvt8(pb2, pb3, bt + boffc1, bt + BPLB + boffc1,
                         bt + 2 * BPLB + boffc1);
                }
                if (c + 2 < NCH) {
                    const float* a = gA + (size_t)(c + 2) * KC;
                    pa0 = *reinterpret_cast<const float4*>(a);
                    pa1 = *reinterpret_cast<const float4*>(a + 4);
                    const float* b0 = gB0 + (size_t)(c + 2) * KC;
                    const float* b1 = gB1 + (size_t)(c + 2) * KC;
                    pb0 = *reinterpret_cast<const float4*>(b0);
                    pb1 = *reinterpret_cast<const float4*>(b0 + 4);
                    pb2 = *reinterpret_cast<const float4*>(b1);
                    pb3 = *reinterpret_cast<const float4*>(b1 + 4);
                }
            }

            // plane 1: A0->cC, A1->cC
            #pragma unroll
            for (int q = 0; q < 2; q++) ldmx4(&Bf[q * 4], Bb + BPLB + boff[q] + kb);
            #pragma unroll
            for (int mt = 0; mt < 2; mt++)
                #pragma unroll
                for (int nt = 0; nt < 4; nt++) {
                    mma16(cC[mt][nt], A0[mt], &Bf[nt * 2]);
                    mma16(cC[mt][nt], A1[mt], &Bf[nt * 2]);
                }

            // plane 2: A0->cC
            #pragma unroll
            for (int q = 0; q < 2; q++) ldmx4(&Bf[q * 4], Bb + 2 * BPLB + boff[q] + kb);
            #pragma unroll
            for (int mt = 0; mt < 2; mt++)
                #pragma unroll
                for (int nt = 0; nt < 4; nt++)
                    mma16(cC[mt][nt], A0[mt], &Bf[nt * 2]);
        }

        __syncthreads();   // stage s reads done; stage s^1 writes visible
    }

    // ---- combine accumulators, write logits [64][132] (stage area reused) ----
    #pragma unroll
    for (int mt = 0; mt < 2; mt++)
        #pragma unroll
        for (int nt = 0; nt < 4; nt++) {
            int r0  = moff + mt * 16 + (lane >> 2);
            int col = noff + nt * 8 + 2 * (lane & 3);
            slog[r0 * LPITCH + col]           = cM[mt][nt][0] + cC[mt][nt][0];
            slog[r0 * LPITCH + col + 1]       = cM[mt][nt][1] + cC[mt][nt][1];
            slog[(r0 + 8) * LPITCH + col]     = cM[mt][nt][2] + cC[mt][nt][2];
            slog[(r0 + 8) * LPITCH + col + 1] = cM[mt][nt][3] + cC[mt][nt][3];
        }

    __syncthreads();

    // ---- top-4 + softmax: one thread per token ----
    if (tid < BM) {
        const float* row = slog + tid * LPITCH;
        float v0 = -1e30f, v1 = -1e30f, v2 = -1e30f, v3 = -1e30f;
        int   i0 = 0,      i1 = 0,      i2 = 0,      i3 = 0;
        #pragma unroll 4
        for (int e = 0; e < EE; e++) {
            float v = row[e] + sbias[e];
            if (v > v3) {               // strict > keeps earliest index on ties
                if (v > v2) {
                    v3 = v2; i3 = i2;
                    if (v > v1) {
                        v2 = v1; i2 = i1;
                        if (v > v0) { v1 = v0; i1 = i0; v0 = v; i0 = e; }
                        else        { v1 = v;  i1 = e; }
                    } else { v2 = v; i2 = e; }
                } else { v3 = v; i3 = e; }
            }
        }
        float e1 = expf(v1 - v0);
        float e2 = expf(v2 - v0);
        float e3 = expf(v3 - v0);
        float inv = 1.0f / (1.0f + e1 + e2 + e3);

        const int t = m0 + tid;
        float* so = out + (size_t)t * TOPK;
        so[0] = inv; so[1] = e1 * inv; so[2] = e2 * inv; so[3] = e3 * inv;
        if (write_idx) {
            float* io = out + (size_t)TT * TOPK + (size_t)t * TOPK;
            io[0] = (float)i0; io[1] = (float)i1;
            io[2] = (float)i2; io[3] = (float)i3;
        }
    }
}

extern "C" void kernel_launch(void* const* d_in, const int* in_sizes, int n_in,
                              void* d_out, int out_size) {
    const float* hs   = (const float*)d_in[0];
    const float* wt   = (const float*)d_in[1];
    const float* bias = (const float*)d_in[2];
    float* out = (float*)d_out;

    const int write_idx = (out_size >= 2 * TT * TOPK) ? 1 : 0;

    cudaFuncSetAttribute(router_hmma,
                         cudaFuncAttributeMaxDynamicSharedMemorySize, SMEM_BYTES);
    router_hmma<<<TT / BM, 256, SMEM_BYTES>>>(hs, wt, bias, out, write_idx);
}

// round 12
// speedup vs baseline: 1.3255x; 1.2203x over previous
#include <cuda_runtime.h>
#include <cstdint>

// GptOssTopKRouter via mma.sync bf16 (compute_103-safe tensor path).
// logits = hs[16384,2880] @ w[128,2880]^T + bias -> top-4 -> softmax.
// Output f32: scores[T*4] ++ indices[T*4].
//
// fp32 via 3-plane bf16 Dekker split, 6 plane-products; main (a0b0) in its
// own fp32 accumulator set, corrections in a second set.
// R12 (base = R8, best): W's 3 bf16 planes precomputed ONCE by a prep kernel
// into __device__ scratch; main kernel stages B via cp.async.ca pure copies
// (no cvt ALU, no prefetch regs). Freed registers fund a B-fragment double
// buffer. A-side keeps the R8 LDG+cvt path.

#define TT    16384
#define HH    2880
#define EE    128
#define TOPK  4
#define BM    128
#define KC    32
#define NCH   (HH / KC)        // 90

#define PITCH  80              // bytes/row (conflict-free for ldmatrix/STS)
#define PLB    (128 * PITCH)   // 10240 B per plane
#define STG    (6 * PLB)       // A0 A1 A2 B0 B1 B2 = 61440 B
#define BOFS   (3 * PLB)
#define SMOFF  512
#define LPITCH 132
#define SMEM_BYTES (SMOFF + 2 * STG)   // 123392 (logits reuse stage area)

// Precomputed W planes: [chunk][plane][row][64B of bf16]
__device__ __align__(16) unsigned char g_wplanes[NCH * 3 * 128 * 64];

__device__ __forceinline__ uint32_t s2u(const void* p) {
    uint32_t a;
    asm("{ .reg .u64 t; cvta.to.shared.u64 t, %1; cvt.u32.u64 %0, t; }"
        : "=r"(a) : "l"(p));
    return a;
}
__device__ __forceinline__ uint32_t pack_bf16x2(float hi, float lo) {
    uint32_t r;
    asm("cvt.rn.bf16x2.f32 %0, %1, %2;" : "=r"(r) : "f"(hi), "f"(lo));
    return r;
}
__device__ __forceinline__ void ldmx4(uint32_t* r, uint32_t addr) {
    asm volatile("ldmatrix.sync.aligned.m8n8.x4.shared.b16 {%0,%1,%2,%3}, [%4];"
                 : "=r"(r[0]), "=r"(r[1]), "=r"(r[2]), "=r"(r[3]) : "r"(addr));
}
__device__ __forceinline__ void mma16(float* c, const uint32_t* a, const uint32_t* b) {
    asm("mma.sync.aligned.m16n8k16.row.col.f32.bf16.bf16.f32 "
        "{%0,%1,%2,%3}, {%4,%5,%6,%7}, {%8,%9}, {%0,%1,%2,%3};"
        : "+f"(c[0]), "+f"(c[1]), "+f"(c[2]), "+f"(c[3])
        : "r"(a[0]), "r"(a[1]), "r"(a[2]), "r"(a[3]), "r"(b[0]), "r"(b[1]));
}
__device__ __forceinline__ void cpa16(uint32_t dst, const void* src) {
    asm volatile("cp.async.ca.shared.global [%0], [%1], 16;"
                 :: "r"(dst), "l"(src) : "memory");
}
#define CP_COMMIT() asm volatile("cp.async.commit_group;" ::: "memory")
#define CP_WAIT0()  asm volatile("cp.async.wait_group 0;" ::: "memory")

// 8 fp32 -> 3 bf16x2-quads (Dekker exact split).
__device__ __forceinline__ void split8(const float4& f0, const float4& f1,
                                       uint32_t* q0, uint32_t* q1, uint32_t* q2) {
    float x[8] = {f0.x, f0.y, f0.z, f0.w, f1.x, f1.y, f1.z, f1.w};
    #pragma unroll
    for (int q = 0; q < 4; q++) {
        float a = x[2 * q], b = x[2 * q + 1];
        uint32_t h = pack_bf16x2(b, a);             // lo=bf16(a), hi=bf16(b)
        float ha = __uint_as_float(h << 16);
        float hb = __uint_as_float(h & 0xFFFF0000u);
        float ra = a - ha, rb = b - hb;             // exact
        uint32_t m = pack_bf16x2(rb, ra);
        float ma = __uint_as_float(m << 16);
        float mb = __uint_as_float(m & 0xFFFF0000u);
        q2[q] = pack_bf16x2(rb - mb, ra - ma);      // exact residual
        q0[q] = h; q1[q] = m;
    }
}

// Prep kernel: W fp32 -> 3 bf16 planes in g_wplanes. One thread per
// (chunk, row, 16B-block): 90*128*4 = 46080 threads.
__global__ void prep_w(const float* __restrict__ wt) {
    int t = blockIdx.x * blockDim.x + threadIdx.x;
    if (t >= NCH * 128 * 4) return;
    int kq = t & 3;
    int r  = (t >> 2) & 127;
    int c  = t >> 9;
    const float* src = wt + (size_t)r * HH + c * KC + kq * 8;
    float4 f0 = *reinterpret_cast<const float4*>(src);
    float4 f1 = *reinterpret_cast<const float4*>(src + 4);
    uint32_t q0[4], q1[4], q2[4];
    split8(f0, f1, q0, q1, q2);
    size_t base = ((size_t)(c * 3) * 128 + r) * 64 + kq * 16;
    *reinterpret_cast<uint4*>(g_wplanes + base)
        = make_uint4(q0[0], q0[1], q0[2], q0[3]);
    *reinterpret_cast<uint4*>(g_wplanes + base + 128 * 64)
        = make_uint4(q1[0], q1[1], q1[2], q1[3]);
    *reinterpret_cast<uint4*>(g_wplanes + base + 2 * 128 * 64)
        = make_uint4(q2[0], q2[1], q2[2], q2[3]);
}

__global__ __launch_bounds__(512, 1)
void router_hmma(const float* __restrict__ hs,
                 const float* __restrict__ bias,
                 float* __restrict__ out,
                 int write_idx)
{
    extern __shared__ char smem[];
    float* sbias = reinterpret_cast<float*>(smem);
    float* slog  = reinterpret_cast<float*>(smem + SMOFF);
    const uint32_t sb = s2u(smem);

    const int tid  = threadIdx.x;
    const int wid  = tid >> 5;
    const int lane = tid & 31;
    const int m0   = blockIdx.x * BM;

    if (tid < EE) sbias[tid] = bias[tid];

    // ---- A convert mapping: 4 threads per row, 8 fp32 each ----
    const int crow = tid >> 2;
    const int ckq  = (tid & 3) * 8;
    const float* gA = hs + (size_t)(m0 + crow) * HH + ckq;
    const int aoffc = crow * PITCH + ckq * 2;

    // ---- B copy mapping: one 16B block per plane per thread ----
    const int brow = tid >> 2;
    const int bkq  = tid & 3;
    const uint32_t bdst = (uint32_t)(brow * PITCH + bkq * 16);
    const size_t   bsrc = ((size_t)brow) * 64 + bkq * 16;

    // ---- mma mapping: 16 warps = 4M x 4N; warp tile 32x32 ----
    const int moff = (wid & 3) * 32;
    const int noff = (wid >> 2) * 32;
    const int mt8  = lane >> 3;
    const int mr   = lane & 7;
    uint32_t aoff[2], boff[2];
    #pragma unroll
    for (int mt = 0; mt < 2; mt++)
        aoff[mt] = (uint32_t)((moff + mt * 16 + ((mt8 & 1) << 3) + mr) * PITCH
                              + (((mt8 >> 1) << 3) << 1));
    #pragma unroll
    for (int q = 0; q < 2; q++)
        boff[q] = (uint32_t)((noff + q * 16 + ((mt8 >> 1) << 3) + mr) * PITCH
                             + (((mt8 & 1) << 3) << 1));

    float cM[2][4][4], cC[2][4][4];
    #pragma unroll
    for (int i = 0; i < 2; i++)
        #pragma unroll
        for (int j = 0; j < 4; j++)
            #pragma unroll
            for (int q = 0; q < 4; q++) { cM[i][j][q] = 0.0f; cC[i][j][q] = 0.0f; }

    auto issueB = [&](int c) {   // stage (c&1); 3 planes, 16B each
        uint32_t dst = sb + SMOFF + (c & 1) * STG + BOFS + bdst;
        const unsigned char* src = g_wplanes + ((size_t)(c * 3) * 128) * 64 + bsrc;
        cpa16(dst,           src);
        cpa16(dst + PLB,     src + 128 * 64);
        cpa16(dst + 2 * PLB, src + 2 * 128 * 64);
        CP_COMMIT();
    };
    auto cvtA = [&](int c, const float4& f0, const float4& f1) {
        uint32_t q0[4], q1[4], q2[4];
        split8(f0, f1, q0, q1, q2);
        char* st = smem + SMOFF + (c & 1) * STG;
        *reinterpret_cast<uint4*>(st + aoffc)
            = make_uint4(q0[0], q0[1], q0[2], q0[3]);
        *reinterpret_cast<uint4*>(st + PLB + aoffc)
            = make_uint4(q1[0], q1[1], q1[2], q1[3]);
        *reinterpret_cast<uint4*>(st + 2 * PLB + aoffc)
            = make_uint4(q2[0], q2[1], q2[2], q2[3]);
    };

    // ---- prologue: A(0) cvt, B(0) copy, prefetch A(1) ----
    float4 pa0 = *reinterpret_cast<const float4*>(gA);
    float4 pa1 = *reinterpret_cast<const float4*>(gA + 4);
    issueB(0);
    cvtA(0, pa0, pa1);
    pa0 = *reinterpret_cast<const float4*>(gA + KC);
    pa1 = *reinterpret_cast<const float4*>(gA + KC + 4);
    CP_WAIT0();
    __syncthreads();

    for (int c = 0; c < NCH; c++) {
        const int s = c & 1;
        const uint32_t Ab = sb + SMOFF + s * STG;
        const uint32_t Bb = Ab + BOFS;

        #pragma unroll
        for (int ks = 0; ks < 2; ks++) {
            const uint32_t kb = ks * 32;       // 16 K-cols = 32 bytes

            uint32_t A0[2][4], A1[2][4], A2[2][4], Bf0[8], Bf1[8];
            #pragma unroll
            for (int q = 0; q < 2; q++) ldmx4(&Bf0[q * 4], Bb + boff[q] + kb);
            #pragma unroll
            for (int mt = 0; mt < 2; mt++) ldmx4(A0[mt], Ab + aoff[mt] + kb);
            #pragma unroll
            for (int mt = 0; mt < 2; mt++) ldmx4(A1[mt], Ab + PLB + aoff[mt] + kb);
            #pragma unroll
            for (int mt = 0; mt < 2; mt++) ldmx4(A2[mt], Ab + 2 * PLB + aoff[mt] + kb);
            // B plane 1 prefetched into the second buffer
            #pragma unroll
            for (int q = 0; q < 2; q++) ldmx4(&Bf1[q * 4], Bb + PLB + boff[q] + kb);

            // plane 0: A0->cM, A1->cC, A2->cC
            #pragma unroll
            for (int mt = 0; mt < 2; mt++)
                #pragma unroll
                for (int nt = 0; nt < 4; nt++) {
                    mma16(cM[mt][nt], A0[mt], &Bf0[nt * 2]);
                    mma16(cC[mt][nt], A1[mt], &Bf0[nt * 2]);
                    mma16(cC[mt][nt], A2[mt], &Bf0[nt * 2]);
                }

            // overlapped producer work
            if (ks == 0) {
                if (c + 1 < NCH) {
                    issueB(c + 1);
                    cvtA(c + 1, pa0, pa1);
                }
            } else {
                if (c + 2 < NCH) {
                    const float* a = gA + (size_t)(c + 2) * KC;
                    pa0 = *reinterpret_cast<const float4*>(a);
                    pa1 = *reinterpret_cast<const float4*>(a + 4);
                }
            }

            // plane 2 into Bf0 (plane-0 reads drained)
            #pragma unroll
            for (int q = 0; q < 2; q++)
                ldmx4(&Bf0[q * 4], Bb + 2 * PLB + boff[q] + kb);

            // plane 1: A0->cC, A1->cC
            #pragma unroll
            for (int mt = 0; mt < 2; mt++)
                #pragma unroll
                for (int nt = 0; nt < 4; nt++) {
                    mma16(cC[mt][nt], A0[mt], &Bf1[nt * 2]);
                    mma16(cC[mt][nt], A1[mt], &Bf1[nt * 2]);
                }

            // plane 2: A0->cC
            #pragma unroll
            for (int mt = 0; mt < 2; mt++)
                #pragma unroll
                for (int nt = 0; nt < 4; nt++)
                    mma16(cC[mt][nt], A0[mt], &Bf0[nt * 2]);
        }

        CP_WAIT0();        // B copies for c+1 (issued ~a chunk ago) landed
        __syncthreads();   // stage s reads done; stage s^1 writes visible
    }

    // ---- combine accumulators, write logits [128][132] (stage area reused) ----
    #pragma unroll
    for (int mt = 0; mt < 2; mt++)
        #pragma unroll
        for (int nt = 0; nt < 4; nt++) {
            int r0  = moff + mt * 16 + (lane >> 2);
            int col = noff + nt * 8 + 2 * (lane & 3);
            slog[r0 * LPITCH + col]           = cM[mt][nt][0] + cC[mt][nt][0];
            slog[r0 * LPITCH + col + 1]       = cM[mt][nt][1] + cC[mt][nt][1];
            slog[(r0 + 8) * LPITCH + col]     = cM[mt][nt][2] + cC[mt][nt][2];
            slog[(r0 + 8) * LPITCH + col + 1] = cM[mt][nt][3] + cC[mt][nt][3];
        }

    __syncthreads();

    // ---- top-4 + softmax: one thread per token ----
    if (tid < BM) {
        const float* row = slog + tid * LPITCH;
        float v0 = -1e30f, v1 = -1e30f, v2 = -1e30f, v3 = -1e30f;
        int   i0 = 0,      i1 = 0,      i2 = 0,      i3 = 0;
        #pragma unroll 4
        for (int e = 0; e < EE; e++) {
            float v = row[e] + sbias[e];
            if (v > v3) {               // strict > keeps earliest index on ties
                if (v > v2) {
                    v3 = v2; i3 = i2;
                    if (v > v1) {
                        v2 = v1; i2 = i1;
                        if (v > v0) { v1 = v0; i1 = i0; v0 = v; i0 = e; }
                        else        { v1 = v;  i1 = e; }
                    } else { v2 = v; i2 = e; }
                } else { v3 = v; i3 = e; }
            }
        }
        float e1 = expf(v1 - v0);
        float e2 = expf(v2 - v0);
        float e3 = expf(v3 - v0);
        float inv = 1.0f / (1.0f + e1 + e2 + e3);

        const int t = m0 + tid;
        float* so = out + (size_t)t * TOPK;
        so[0] = inv; so[1] = e1 * inv; so[2] = e2 * inv; so[3] = e3 * inv;
        if (write_idx) {
            float* io = out + (size_t)TT * TOPK + (size_t)t * TOPK;
            io[0] = (float)i0; io[1] = (float)i1;
            io[2] = (float)i2; io[3] = (float)i3;
        }
    }
}

extern "C" void kernel_launch(void* const* d_in, const int* in_sizes, int n_in,
                              void* d_out, int out_size) {
    const float* hs   = (const float*)d_in[0];
    const float* wt   = (const float*)d_in[1];
    const float* bias = (const float*)d_in[2];
    float* out = (float*)d_out;

    const int write_idx = (out_size >= 2 * TT * TOPK) ? 1 : 0;

    prep_w<<<(NCH * 128 * 4 + 255) / 256, 256>>>(wt);

    cudaFuncSetAttribute(router_hmma,
                         cudaFuncAttributeMaxDynamicSharedMemorySize, SMEM_BYTES);
    router_hmma<<<TT / BM, 512, SMEM_BYTES>>>(hs, bias, out, write_idx);
}

// round 17
// speedup vs baseline: 1.3257x; 1.0002x over previous
#include <cuda_runtime.h>
#include <cstdint>

// GptOssTopKRouter via mma.sync bf16 (compute_103-safe tensor path).
// logits = hs[16384,2880] @ w[128,2880]^T + bias -> top-4 -> softmax.
// Output f32: scores[T*4] ++ indices[T*4].
//
// fp32 via 3-plane bf16 Dekker split, 6 plane-products; main (a0b0) in its
// own fp32 accumulator set, corrections in a second set.
// R13 (= R12 + separated MMA loop nests): consecutive writes to the same
// accumulator register are now 8 MMAs apart (was 1) so HMMA result latency
// is covered by independent work instead of stalling the warp.

#define TT    16384
#define HH    2880
#define EE    128
#define TOPK  4
#define BM    128
#define KC    32
#define NCH   (HH / KC)        // 90

#define PITCH  80              // bytes/row (conflict-free for ldmatrix/STS)
#define PLB    (128 * PITCH)   // 10240 B per plane
#define STG    (6 * PLB)       // A0 A1 A2 B0 B1 B2 = 61440 B
#define BOFS   (3 * PLB)
#define SMOFF  512
#define LPITCH 132
#define SMEM_BYTES (SMOFF + 2 * STG)   // 123392 (logits reuse stage area)

// Precomputed W planes: [chunk][plane][row][64B of bf16]
__device__ __align__(16) unsigned char g_wplanes[NCH * 3 * 128 * 64];

__device__ __forceinline__ uint32_t s2u(const void* p) {
    uint32_t a;
    asm("{ .reg .u64 t; cvta.to.shared.u64 t, %1; cvt.u32.u64 %0, t; }"
        : "=r"(a) : "l"(p));
    return a;
}
__device__ __forceinline__ uint32_t pack_bf16x2(float hi, float lo) {
    uint32_t r;
    asm("cvt.rn.bf16x2.f32 %0, %1, %2;" : "=r"(r) : "f"(hi), "f"(lo));
    return r;
}
__device__ __forceinline__ void ldmx4(uint32_t* r, uint32_t addr) {
    asm volatile("ldmatrix.sync.aligned.m8n8.x4.shared.b16 {%0,%1,%2,%3}, [%4];"
                 : "=r"(r[0]), "=r"(r[1]), "=r"(r[2]), "=r"(r[3]) : "r"(addr));
}
__device__ __forceinline__ void mma16(float* c, const uint32_t* a, const uint32_t* b) {
    asm("mma.sync.aligned.m16n8k16.row.col.f32.bf16.bf16.f32 "
        "{%0,%1,%2,%3}, {%4,%5,%6,%7}, {%8,%9}, {%0,%1,%2,%3};"
        : "+f"(c[0]), "+f"(c[1]), "+f"(c[2]), "+f"(c[3])
        : "r"(a[0]), "r"(a[1]), "r"(a[2]), "r"(a[3]), "r"(b[0]), "r"(b[1]));
}
__device__ __forceinline__ void cpa16(uint32_t dst, const void* src) {
    asm volatile("cp.async.ca.shared.global [%0], [%1], 16;"
                 :: "r"(dst), "l"(src) : "memory");
}
#define CP_COMMIT() asm volatile("cp.async.commit_group;" ::: "memory")
#define CP_WAIT0()  asm volatile("cp.async.wait_group 0;" ::: "memory")

// 8 fp32 -> 3 bf16x2-quads (Dekker exact split).
__device__ __forceinline__ void split8(const float4& f0, const float4& f1,
                                       uint32_t* q0, uint32_t* q1, uint32_t* q2) {
    float x[8] = {f0.x, f0.y, f0.z, f0.w, f1.x, f1.y, f1.z, f1.w};
    #pragma unroll
    for (int q = 0; q < 4; q++) {
        float a = x[2 * q], b = x[2 * q + 1];
        uint32_t h = pack_bf16x2(b, a);             // lo=bf16(a), hi=bf16(b)
        float ha = __uint_as_float(h << 16);
        float hb = __uint_as_float(h & 0xFFFF0000u);
        float ra = a - ha, rb = b - hb;             // exact
        uint32_t m = pack_bf16x2(rb, ra);
        float ma = __uint_as_float(m << 16);
        float mb = __uint_as_float(m & 0xFFFF0000u);
        q2[q] = pack_bf16x2(rb - mb, ra - ma);      // exact residual
        q0[q] = h; q1[q] = m;
    }
}

// Prep kernel: W fp32 -> 3 bf16 planes. One thread per (chunk,row,16B-block).
__global__ void prep_w(const float* __restrict__ wt) {
    int t = blockIdx.x * blockDim.x + threadIdx.x;
    if (t >= NCH * 128 * 4) return;
    int kq = t & 3;
    int r  = (t >> 2) & 127;
    int c  = t >> 9;
    const float* src = wt + (size_t)r * HH + c * KC + kq * 8;
    float4 f0 = *reinterpret_cast<const float4*>(src);
    float4 f1 = *reinterpret_cast<const float4*>(src + 4);
    uint32_t q0[4], q1[4], q2[4];
    split8(f0, f1, q0, q1, q2);
    size_t base = ((size_t)(c * 3) * 128 + r) * 64 + kq * 16;
    *reinterpret_cast<uint4*>(g_wplanes + base)
        = make_uint4(q0[0], q0[1], q0[2], q0[3]);
    *reinterpret_cast<uint4*>(g_wplanes + base + 128 * 64)
        = make_uint4(q1[0], q1[1], q1[2], q1[3]);
    *reinterpret_cast<uint4*>(g_wplanes + base + 2 * 128 * 64)
        = make_uint4(q2[0], q2[1], q2[2], q2[3]);
}

__global__ __launch_bounds__(512, 1)
void router_hmma(const float* __restrict__ hs,
                 const float* __restrict__ bias,
                 float* __restrict__ out,
                 int write_idx)
{
    extern __shared__ char smem[];
    float* sbias = reinterpret_cast<float*>(smem);
    float* slog  = reinterpret_cast<float*>(smem + SMOFF);
    const uint32_t sb = s2u(smem);

    const int tid  = threadIdx.x;
    const int wid  = tid >> 5;
    const int lane = tid & 31;
    const int m0   = blockIdx.x * BM;

    if (tid < EE) sbias[tid] = bias[tid];

    // ---- A convert mapping: 4 threads per row, 8 fp32 each ----
    const int crow = tid >> 2;
    const int ckq  = (tid & 3) * 8;
    const float* gA = hs + (size_t)(m0 + crow) * HH + ckq;
    const int aoffc = crow * PITCH + ckq * 2;

    // ---- B copy mapping: one 16B block per plane per thread ----
    const int brow = tid >> 2;
    const int bkq  = tid & 3;
    const uint32_t bdst = (uint32_t)(brow * PITCH + bkq * 16);
    const size_t   bsrc = ((size_t)brow) * 64 + bkq * 16;

    // ---- mma mapping: 16 warps = 4M x 4N; warp tile 32x32 ----
    const int moff = (wid & 3) * 32;
    const int noff = (wid >> 2) * 32;
    const int mt8  = lane >> 3;
    const int mr   = lane & 7;
    uint32_t aoff[2], boff[2];
    #pragma unroll
    for (int mt = 0; mt < 2; mt++)
        aoff[mt] = (uint32_t)((moff + mt * 16 + ((mt8 & 1) << 3) + mr) * PITCH
                              + (((mt8 >> 1) << 3) << 1));
    #pragma unroll
    for (int q = 0; q < 2; q++)
        boff[q] = (uint32_t)((noff + q * 16 + ((mt8 >> 1) << 3) + mr) * PITCH
                             + (((mt8 & 1) << 3) << 1));

    float cM[2][4][4], cC[2][4][4];
    #pragma unroll
    for (int i = 0; i < 2; i++)
        #pragma unroll
        for (int j = 0; j < 4; j++)
            #pragma unroll
            for (int q = 0; q < 4; q++) { cM[i][j][q] = 0.0f; cC[i][j][q] = 0.0f; }

    auto issueB = [&](int c) {   // stage (c&1); 3 planes, 16B each
        uint32_t dst = sb + SMOFF + (c & 1) * STG + BOFS + bdst;
        const unsigned char* src = g_wplanes + ((size_t)(c * 3) * 128) * 64 + bsrc;
        cpa16(dst,           src);
        cpa16(dst + PLB,     src + 128 * 64);
        cpa16(dst + 2 * PLB, src + 2 * 128 * 64);
        CP_COMMIT();
    };
    auto cvtA = [&](int c, const float4& f0, const float4& f1) {
        uint32_t q0[4], q1[4], q2[4];
        split8(f0, f1, q0, q1, q2);
        char* st = smem + SMOFF + (c & 1) * STG;
        *reinterpret_cast<uint4*>(st + aoffc)
            = make_uint4(q0[0], q0[1], q0[2], q0[3]);
        *reinterpret_cast<uint4*>(st + PLB + aoffc)
            = make_uint4(q1[0], q1[1], q1[2], q1[3]);
        *reinterpret_cast<uint4*>(st + 2 * PLB + aoffc)
            = make_uint4(q2[0], q2[1], q2[2], q2[3]);
    };

    // ---- prologue: A(0) cvt, B(0) copy, prefetch A(1) ----
    float4 pa0 = *reinterpret_cast<const float4*>(gA);
    float4 pa1 = *reinterpret_cast<const float4*>(gA + 4);
    issueB(0);
    cvtA(0, pa0, pa1);
    pa0 = *reinterpret_cast<const float4*>(gA + KC);
    pa1 = *reinterpret_cast<const float4*>(gA + KC + 4);
    CP_WAIT0();
    __syncthreads();

    for (int c = 0; c < NCH; c++) {
        const int s = c & 1;
        const uint32_t Ab = sb + SMOFF + s * STG;
        const uint32_t Bb = Ab + BOFS;

        #pragma unroll
        for (int ks = 0; ks < 2; ks++) {
            const uint32_t kb = ks * 32;       // 16 K-cols = 32 bytes

            uint32_t A0[2][4], A1[2][4], A2[2][4], Bf0[8], Bf1[8];
            #pragma unroll
            for (int q = 0; q < 2; q++) ldmx4(&Bf0[q * 4], Bb + boff[q] + kb);
            #pragma unroll
            for (int mt = 0; mt < 2; mt++) ldmx4(A0[mt], Ab + aoff[mt] + kb);
            #pragma unroll
            for (int mt = 0; mt < 2; mt++) ldmx4(A1[mt], Ab + PLB + aoff[mt] + kb);
            #pragma unroll
            for (int mt = 0; mt < 2; mt++) ldmx4(A2[mt], Ab + 2 * PLB + aoff[mt] + kb);
            // B plane 1 prefetched into the second buffer
            #pragma unroll
            for (int q = 0; q < 2; q++) ldmx4(&Bf1[q * 4], Bb + PLB + boff[q] + kb);

            // plane 0 — SEPARATED nests: same-register writes 8 apart
            #pragma unroll
            for (int mt = 0; mt < 2; mt++)
                #pragma unroll
                for (int nt = 0; nt < 4; nt++)
                    mma16(cM[mt][nt], A0[mt], &Bf0[nt * 2]);
            #pragma unroll
            for (int mt = 0; mt < 2; mt++)
                #pragma unroll
                for (int nt = 0; nt < 4; nt++)
                    mma16(cC[mt][nt], A1[mt], &Bf0[nt * 2]);
            #pragma unroll
            for (int mt = 0; mt < 2; mt++)
                #pragma unroll
                for (int nt = 0; nt < 4; nt++)
                    mma16(cC[mt][nt], A2[mt], &Bf0[nt * 2]);

            // overlapped producer work
            if (ks == 0) {
                if (c + 1 < NCH) {
                    issueB(c + 1);
                    cvtA(c + 1, pa0, pa1);
                }
            } else {
                if (c + 2 < NCH) {
                    const float* a = gA + (size_t)(c + 2) * KC;
                    pa0 = *reinterpret_cast<const float4*>(a);
                    pa1 = *reinterpret_cast<const float4*>(a + 4);
                }
            }

            // plane 2 into Bf0 (plane-0 reads drained)
            #pragma unroll
            for (int q = 0; q < 2; q++)
                ldmx4(&Bf0[q * 4], Bb + 2 * PLB + boff[q] + kb);

            // plane 1 — separated nests
            #pragma unroll
            for (int mt = 0; mt < 2; mt++)
                #pragma unroll
                for (int nt = 0; nt < 4; nt++)
                    mma16(cC[mt][nt], A0[mt], &Bf1[nt * 2]);
            #pragma unroll
            for (int mt = 0; mt < 2; mt++)
                #pragma unroll
                for (int nt = 0; nt < 4; nt++)
                    mma16(cC[mt][nt], A1[mt], &Bf1[nt * 2]);

            // plane 2
            #pragma unroll
            for (int mt = 0; mt < 2; mt++)
                #pragma unroll
                for (int nt = 0; nt < 4; nt++)
                    mma16(cC[mt][nt], A0[mt], &Bf0[nt * 2]);
        }

        CP_WAIT0();        // B copies for c+1 landed
        __syncthreads();   // stage s reads done; stage s^1 writes visible
    }

    // ---- combine accumulators, write logits [128][132] (stage area reused) ----
    #pragma unroll
    for (int mt = 0; mt < 2; mt++)
        #pragma unroll
        for (int nt = 0; nt < 4; nt++) {
            int r0  = moff + mt * 16 + (lane >> 2);
            int col = noff + nt * 8 + 2 * (lane & 3);
            slog[r0 * LPITCH + col]           = cM[mt][nt][0] + cC[mt][nt][0];
            slog[r0 * LPITCH + col + 1]       = cM[mt][nt][1] + cC[mt][nt][1];
            slog[(r0 + 8) * LPITCH + col]     = cM[mt][nt][2] + cC[mt][nt][2];
            slog[(r0 + 8) * LPITCH + col + 1] = cM[mt][nt][3] + cC[mt][nt][3];
        }

    __syncthreads();

    // ---- top-4 + softmax: one thread per token ----
    if (tid < BM) {
        const float* row = slog + tid * LPITCH;
        float v0 = -1e30f, v1 = -1e30f, v2 = -1e30f, v3 = -1e30f;
        int   i0 = 0,      i1 = 0,      i2 = 0,      i3 = 0;
        #pragma unroll 4
        for (int e = 0; e < EE; e++) {
            float v = row[e] + sbias[e];
            if (v > v3) {               // strict > keeps earliest index on ties
                if (v > v2) {
                    v3 = v2; i3 = i2;
                    if (v > v1) {
                        v2 = v1; i2 = i1;
                        if (v > v0) { v1 = v0; i1 = i0; v0 = v; i0 = e; }
                        else        { v1 = v;  i1 = e; }
                    } else { v2 = v; i2 = e; }
                } else { v3 = v; i3 = e; }
            }
        }
        float e1 = expf(v1 - v0);
        float e2 = expf(v2 - v0);
        float e3 = expf(v3 - v0);
        float inv = 1.0f / (1.0f + e1 + e2 + e3);

        const int t = m0 + tid;
        float* so = out + (size_t)t * TOPK;
        so[0] = inv; so[1] = e1 * inv; so[2] = e2 * inv; so[3] = e3 * inv;
        if (write_idx) {
            float* io = out + (size_t)TT * TOPK + (size_t)t * TOPK;
            io[0] = (float)i0; io[1] = (float)i1;
            io[2] = (float)i2; io[3] = (float)i3;
        }
    }
}

extern "C" void kernel_launch(void* const* d_in, const int* in_sizes, int n_in,
                              void* d_out, int out_size) {
    const float* hs   = (const float*)d_in[0];
    const float* wt   = (const float*)d_in[1];
    const float* bias = (const float*)d_in[2];
    float* out = (float*)d_out;

    const int write_idx = (out_size >= 2 * TT * TOPK) ? 1 : 0;

    prep_w<<<(NCH * 128 * 4 + 255) / 256, 256>>>(wt);

    cudaFuncSetAttribute(router_hmma,
                         cudaFuncAttributeMaxDynamicSharedMemorySize, SMEM_BYTES);
    router_hmma<<<TT / BM, 512, SMEM_BYTES>>>(hs, bias, out, write_idx);
}